// round 13
// baseline (speedup 1.0000x reference)
#include <cuda_runtime.h>
#include <cuda_bf16.h>
#include <math_constants.h>
#include <cstdint>

// ---------------------------------------------------------------------------
// CrossAttention: out = softmax((xWq)(ctxWk)^T * scale) (ctxWv) Wo + bo
// Round 12: resubmission of the R10 kernel (prior bench was a broker/container
// failure, not a kernel failure — same as round 2's transient).
// Changes vs R9 baseline: merged prep + merged QKV projection launch;
// GEMM occupancy 2; exp2-domain softmax (log2e folded into Q scale).
// ---------------------------------------------------------------------------

#define B_     4
#define NQ     2048
#define NK     1024
#define DQ     512
#define DC     768
#define HEADS  8
#define DHEAD  64
#define INNER  512
#define MQ_ALL (B_*NQ)        // 8192
#define MK_ALL (B_*NK)        // 4096
#define QSCALE (0.125f * 1.44269504f)   // head scale * log2(e)  (exp2 softmax)

// pre-split activations / intermediates (bf16 hi/lo pairs)
__device__ __nv_bfloat16 g_xh [MQ_ALL * DQ],    g_xl [MQ_ALL * DQ];
__device__ __nv_bfloat16 g_ch [MK_ALL * DC],    g_cl [MK_ALL * DC];
__device__ __nv_bfloat16 g_qh [MQ_ALL * INNER], g_ql [MQ_ALL * INNER];
__device__ __nv_bfloat16 g_kh [MK_ALL * INNER], g_kl [MK_ALL * INNER];
__device__ __nv_bfloat16 g_vh [MK_ALL * INNER], g_vl [MK_ALL * INNER];
__device__ __nv_bfloat16 g_aoh[MQ_ALL * INNER], g_aol[MQ_ALL * INNER];

// transposed+split weights [N][K]
#define OFF_WQ 0
#define OFF_WK (512*512)
#define OFF_WV (OFF_WK + 512*768)
#define OFF_WO (OFF_WV + 512*768)
#define WT_TOTAL (OFF_WO + 512*512)
__device__ __nv_bfloat16 g_wthi[WT_TOTAL];
__device__ __nv_bfloat16 g_wtlo[WT_TOTAL];

// ---------------------------------------------------------------------------
// helpers
// ---------------------------------------------------------------------------
__device__ __forceinline__ uint32_t smem_u32(const void* p) {
    uint32_t a;
    asm("{ .reg .u64 t; cvta.to.shared.u64 t, %1; cvt.u32.u64 %0, t; }"
        : "=r"(a) : "l"(p));
    return a;
}
__device__ __forceinline__ void cp16(uint32_t saddr, const void* g) {
    asm volatile("cp.async.cg.shared.global [%0], [%1], 16;"
                 :: "r"(saddr), "l"(g));
}
__device__ __forceinline__ void cp_commit() {
    asm volatile("cp.async.commit_group;" ::: "memory");
}
template <int N> __device__ __forceinline__ void cp_wait() {
    asm volatile("cp.async.wait_group %0;" :: "n"(N) : "memory");
}
__device__ __forceinline__ void ldsm_x4(uint32_t& r0, uint32_t& r1,
                                        uint32_t& r2, uint32_t& r3, uint32_t addr) {
    asm volatile("ldmatrix.sync.aligned.m8n8.x4.shared.b16 {%0,%1,%2,%3}, [%4];"
                 : "=r"(r0), "=r"(r1), "=r"(r2), "=r"(r3) : "r"(addr));
}
__device__ __forceinline__ void ldsm_x4_t(uint32_t& r0, uint32_t& r1,
                                          uint32_t& r2, uint32_t& r3, uint32_t addr) {
    asm volatile("ldmatrix.sync.aligned.m8n8.x4.trans.shared.b16 {%0,%1,%2,%3}, [%4];"
                 : "=r"(r0), "=r"(r1), "=r"(r2), "=r"(r3) : "r"(addr));
}
__device__ __forceinline__ void mma16816(float* c, const uint32_t* a,
                                         uint32_t b0, uint32_t b1) {
    asm volatile(
        "mma.sync.aligned.m16n8k16.row.col.f32.bf16.bf16.f32 "
        "{%0,%1,%2,%3}, {%4,%5,%6,%7}, {%8,%9}, {%0,%1,%2,%3};"
        : "+f"(c[0]), "+f"(c[1]), "+f"(c[2]), "+f"(c[3])
        : "r"(a[0]), "r"(a[1]), "r"(a[2]), "r"(a[3]), "r"(b0), "r"(b1));
}
__device__ __forceinline__ uint32_t packbf2(float a, float b) {
    __nv_bfloat162 t = __floats2bfloat162_rn(a, b);
    return *reinterpret_cast<uint32_t*>(&t);
}
__device__ __forceinline__ float bfhi(float x) {
    return __bfloat162float(__float2bfloat16(x));
}

// ---------------------------------------------------------------------------
// Merged weight transpose+split: all 4 weights in one launch (z selects).
// ---------------------------------------------------------------------------
__global__ void __launch_bounds__(256)
wsplit_all(const float* __restrict__ Wq, const float* __restrict__ Wk,
           const float* __restrict__ Wv, const float* __restrict__ Wo,
           __nv_bfloat16* __restrict__ hi, __nv_bfloat16* __restrict__ lo)
{
    const float* W; __nv_bfloat16 *H, *L; int K, N;
    switch (blockIdx.z) {
        case 0: W = Wq; H = hi + OFF_WQ; L = lo + OFF_WQ; K = DQ;    N = INNER; break;
        case 1: W = Wk; H = hi + OFF_WK; L = lo + OFF_WK; K = DC;    N = INNER; break;
        case 2: W = Wv; H = hi + OFF_WV; L = lo + OFF_WV; K = DC;    N = INNER; break;
        default:W = Wo; H = hi + OFF_WO; L = lo + OFF_WO; K = INNER; N = DQ;    break;
    }
    const int k0 = blockIdx.x * 32, n0 = blockIdx.y * 32;
    if (k0 >= K) return;
    __shared__ float t[32][33];
    const int tx = threadIdx.x & 31, ty = threadIdx.x >> 5;
    #pragma unroll
    for (int i = 0; i < 32; i += 8)
        t[ty + i][tx] = W[(size_t)(k0 + ty + i) * N + n0 + tx];
    __syncthreads();
    #pragma unroll
    for (int i = 0; i < 32; i += 8) {
        float x = t[tx][ty + i];
        __nv_bfloat16 h = __float2bfloat16(x);
        __nv_bfloat16 l = __float2bfloat16(x - __bfloat162float(h));
        size_t o = (size_t)(n0 + ty + i) * K + k0 + tx;
        H[o] = h; L[o] = l;
    }
}

// ---------------------------------------------------------------------------
// Merged activation split: x then ctx in one grid.
// ---------------------------------------------------------------------------
#define NX4 (MQ_ALL * DQ / 4)      // 1048576
#define NC4 (MK_ALL * DC / 4)      // 786432

__global__ void __launch_bounds__(256)
asplit_all(const float* __restrict__ X, const float* __restrict__ CTX,
           __nv_bfloat16* __restrict__ xh, __nv_bfloat16* __restrict__ xl,
           __nv_bfloat16* __restrict__ chp, __nv_bfloat16* __restrict__ clp)
{
    int i = blockIdx.x * 256 + threadIdx.x;
    const float* A; __nv_bfloat16 *H, *L;
    if (i < NX4) { A = X; H = xh; L = xl; }
    else if (i < NX4 + NC4) { i -= NX4; A = CTX; H = chp; L = clp; }
    else return;
    float4 v = ((const float4*)A)[i];
    ((uint2*)H)[i] = make_uint2(packbf2(v.x, v.y), packbf2(v.z, v.w));
    ((uint2*)L)[i] = make_uint2(packbf2(v.x - bfhi(v.x), v.y - bfhi(v.y)),
                                packbf2(v.z - bfhi(v.z), v.w - bfhi(v.w)));
}

// ---------------------------------------------------------------------------
// GEMM core (all-bf16 operands, split 3-MMA): C[128,128]@(m0,n0) =
// A[M,K] @ B^T[512,K]. Output fp32+bias or split hi/lo with scale.
// ---------------------------------------------------------------------------
#define GS_AH 0
#define GS_AL 10240
#define GS_BH 20480
#define GS_BL 30720
#define GS_BUF 40960
#define GEMM_SMEM (2 * GS_BUF)

__device__ __forceinline__ void
gemm_core(const __nv_bfloat16* __restrict__ Ahi, const __nv_bfloat16* __restrict__ Alo,
          const __nv_bfloat16* __restrict__ Bhi, const __nv_bfloat16* __restrict__ Blo,
          const float* __restrict__ bias, float* __restrict__ Cf,
          __nv_bfloat16* __restrict__ Chi, __nv_bfloat16* __restrict__ Clo,
          float scale, int K, int m0, int n0, char* smem)
{
    const uint32_t sb = smem_u32(smem);
    const int tid  = threadIdx.x;
    const int lane = tid & 31;
    const int wid  = tid >> 5;
    const int wm   = (wid & 1) * 64;
    const int wn   = (wid >> 1) * 32;

    float acc[4][4][4];
    #pragma unroll
    for (int mi = 0; mi < 4; ++mi)
        #pragma unroll
        for (int ni = 0; ni < 4; ++ni)
            #pragma unroll
            for (int r = 0; r < 4; ++r) acc[mi][ni][r] = 0.f;

    const int nch = K >> 5;
    const int lr = lane & 15;
    const int lc = (lane >> 4) << 3;

    #pragma unroll
    for (int i = 0; i < 2; ++i) {
        int idx = tid + i * 256;
        int row = idx >> 2, g = idx & 3;
        uint32_t so = (uint32_t)(row * 80 + g * 16);
        cp16(sb + GS_AH + so, Ahi + (size_t)(m0 + row) * K + g * 8);
        cp16(sb + GS_AL + so, Alo + (size_t)(m0 + row) * K + g * 8);
        cp16(sb + GS_BH + so, Bhi + (size_t)(n0 + row) * K + g * 8);
        cp16(sb + GS_BL + so, Blo + (size_t)(n0 + row) * K + g * 8);
    }
    cp_commit();

    for (int c = 0; c < nch; ++c) {
        const uint32_t bufo = (uint32_t)((c & 1) * GS_BUF);
        const bool more = (c + 1 < nch);
        if (more) {
            const int k0n = (c + 1) << 5;
            const uint32_t nb = (uint32_t)(((c + 1) & 1) * GS_BUF);
            #pragma unroll
            for (int i = 0; i < 2; ++i) {
                int idx = tid + i * 256;
                int row = idx >> 2, g = idx & 3;
                uint32_t so = (uint32_t)(row * 80 + g * 16);
                cp16(sb + nb + GS_AH + so, Ahi + (size_t)(m0 + row) * K + k0n + g * 8);
                cp16(sb + nb + GS_AL + so, Alo + (size_t)(m0 + row) * K + k0n + g * 8);
                cp16(sb + nb + GS_BH + so, Bhi + (size_t)(n0 + row) * K + k0n + g * 8);
                cp16(sb + nb + GS_BL + so, Blo + (size_t)(n0 + row) * K + k0n + g * 8);
            }
            cp_commit();
            cp_wait<1>();
        } else {
            cp_wait<0>();
        }
        __syncthreads();

        #pragma unroll
        for (int ks = 0; ks < 32; ks += 16) {
            uint32_t ah[4][4], al[4][4], bh[2][4], bl[2][4];
            #pragma unroll
            for (int mi = 0; mi < 4; ++mi) {
                uint32_t off = (uint32_t)((wm + mi * 16 + lr) * 80 + (ks + lc) * 2);
                ldsm_x4(ah[mi][0], ah[mi][1], ah[mi][2], ah[mi][3], sb + bufo + GS_AH + off);
                ldsm_x4(al[mi][0], al[mi][1], al[mi][2], al[mi][3], sb + bufo + GS_AL + off);
            }
            #pragma unroll
            for (int nt = 0; nt < 2; ++nt) {
                uint32_t off = (uint32_t)((wn + nt * 16 + lr) * 80 + (ks + lc) * 2);
                ldsm_x4(bh[nt][0], bh[nt][1], bh[nt][2], bh[nt][3], sb + bufo + GS_BH + off);
                ldsm_x4(bl[nt][0], bl[nt][1], bl[nt][2], bl[nt][3], sb + bufo + GS_BL + off);
            }
            #pragma unroll
            for (int mi = 0; mi < 4; ++mi)
                #pragma unroll
                for (int ni = 0; ni < 4; ++ni) {
                    int nt = ni >> 1, sel = ni & 1;
                    mma16816(acc[mi][ni], ah[mi], bh[nt][sel], bh[nt][sel + 2]);
                    mma16816(acc[mi][ni], ah[mi], bl[nt][sel], bl[nt][sel + 2]);
                    mma16816(acc[mi][ni], al[mi], bh[nt][sel], bh[nt][sel + 2]);
                }
        }
        __syncthreads();
    }

    const int qrow = lane >> 2;
    const int qcol = (lane & 3) * 2;
    #pragma unroll
    for (int mi = 0; mi < 4; ++mi) {
        #pragma unroll
        for (int ni = 0; ni < 4; ++ni) {
            int row0 = m0 + wm + mi * 16 + qrow;
            int col  = n0 + wn + ni * 8 + qcol;
            if (Cf) {
                float2 o0 = make_float2(acc[mi][ni][0], acc[mi][ni][1]);
                float2 o1 = make_float2(acc[mi][ni][2], acc[mi][ni][3]);
                float2 bb = *(const float2*)&bias[col];
                o0.x += bb.x; o0.y += bb.y;
                o1.x += bb.x; o1.y += bb.y;
                *(float2*)&Cf[(size_t)row0 * 512 + col]       = o0;
                *(float2*)&Cf[(size_t)(row0 + 8) * 512 + col] = o1;
            } else {
                float v0 = acc[mi][ni][0] * scale, v1 = acc[mi][ni][1] * scale;
                float v2 = acc[mi][ni][2] * scale, v3 = acc[mi][ni][3] * scale;
                *(uint32_t*)&Chi[(size_t)row0 * 512 + col] = packbf2(v0, v1);
                *(uint32_t*)&Clo[(size_t)row0 * 512 + col] =
                    packbf2(v0 - bfhi(v0), v1 - bfhi(v1));
                *(uint32_t*)&Chi[(size_t)(row0 + 8) * 512 + col] = packbf2(v2, v3);
                *(uint32_t*)&Clo[(size_t)(row0 + 8) * 512 + col] =
                    packbf2(v2 - bfhi(v2), v3 - bfhi(v3));
            }
        }
    }
}

// Merged Q/K/V projection: grid (4, 128). by<64: Q rows; by<96: K; else V.
__global__ void __launch_bounds__(256, 2)
proj_qkv(const __nv_bfloat16* __restrict__ xh,  const __nv_bfloat16* __restrict__ xl,
         const __nv_bfloat16* __restrict__ ch,  const __nv_bfloat16* __restrict__ cl,
         const __nv_bfloat16* __restrict__ whi, const __nv_bfloat16* __restrict__ wlo,
         __nv_bfloat16* __restrict__ qh,  __nv_bfloat16* __restrict__ ql,
         __nv_bfloat16* __restrict__ kh,  __nv_bfloat16* __restrict__ kl,
         __nv_bfloat16* __restrict__ vh,  __nv_bfloat16* __restrict__ vl)
{
    extern __shared__ char smem[];
    const int by = blockIdx.y;
    const __nv_bfloat16 *Ah, *Al, *Bh, *Bl;
    __nv_bfloat16 *Oh, *Ol;
    float sc; int K, m0;
    if (by < 64) {
        Ah = xh; Al = xl; Bh = whi + OFF_WQ; Bl = wlo + OFF_WQ;
        Oh = qh; Ol = ql; sc = QSCALE; K = DQ; m0 = by * 128;
    } else if (by < 96) {
        Ah = ch; Al = cl; Bh = whi + OFF_WK; Bl = wlo + OFF_WK;
        Oh = kh; Ol = kl; sc = 1.0f; K = DC; m0 = (by - 64) * 128;
    } else {
        Ah = ch; Al = cl; Bh = whi + OFF_WV; Bl = wlo + OFF_WV;
        Oh = vh; Ol = vl; sc = 1.0f; K = DC; m0 = (by - 96) * 128;
    }
    gemm_core(Ah, Al, Bh, Bl, nullptr, nullptr, Oh, Ol, sc, K,
              m0, blockIdx.x * 128, smem);
}

// Output projection (fp32 + bias into d_out)
__global__ void __launch_bounds__(256, 2)
proj_o(const __nv_bfloat16* __restrict__ aoh, const __nv_bfloat16* __restrict__ aol,
       const __nv_bfloat16* __restrict__ whi, const __nv_bfloat16* __restrict__ wlo,
       const float* __restrict__ bias, float* __restrict__ out)
{
    extern __shared__ char smem[];
    gemm_core(aoh, aol, whi + OFF_WO, wlo + OFF_WO, bias, out,
              nullptr, nullptr, 1.0f, INNER,
              blockIdx.y * 128, blockIdx.x * 128, smem);
}

// ---------------------------------------------------------------------------
// Flash attention (R9 core, exp2 softmax). CTA = (b,h) x 128 q-rows.
// ---------------------------------------------------------------------------
#define AT_KH 0
#define AT_KL 18432
#define AT_VH 36864
#define AT_VL 55296
#define AT_BUF 73728
#define ATTN_SMEM (2 * AT_BUF)     // 147456

__global__ void __launch_bounds__(256, 1)
attn_mma(const __nv_bfloat16* __restrict__ qh_, const __nv_bfloat16* __restrict__ ql_,
         const __nv_bfloat16* __restrict__ kh_, const __nv_bfloat16* __restrict__ kl_,
         const __nv_bfloat16* __restrict__ vh_, const __nv_bfloat16* __restrict__ vl_,
         __nv_bfloat16* __restrict__ aoh, __nv_bfloat16* __restrict__ aol)
{
    extern __shared__ char smem[];
    const uint32_t sb = smem_u32(smem);
    const int tid  = threadIdx.x;
    const int lane = tid & 31;
    const int wid  = tid >> 5;
    const int wq   = wid * 16;
    const int lr   = lane & 15;
    const int lc   = (lane >> 4) << 3;

    const int bh = blockIdx.y;
    const int b  = bh >> 3;
    const int h  = bh & 7;
    const int qbase = b * NQ + blockIdx.x * 128;
    const int kbase = b * NK;
    const int hcol  = h * DHEAD;

    // ---- stage Q tile (pre-scaled by QSCALE, pre-split) through buf0 ----
    #pragma unroll
    for (int i = 0; i < 4; ++i) {
        int idx = tid + i * 256;
        int row = idx >> 3, g = idx & 7;
        size_t go = (size_t)(qbase + row) * INNER + hcol + g * 8;
        uint32_t so = (uint32_t)(row * 144 + g * 16);
        *(uint4*)(smem + AT_KH + so) = *(const uint4*)&qh_[go];
        *(uint4*)(smem + AT_KL + so) = *(const uint4*)&ql_[go];
    }
    __syncthreads();

    uint32_t qh[4][4], ql[4][4];
    #pragma unroll
    for (int ks = 0; ks < 4; ++ks) {
        uint32_t off = (uint32_t)((wq + lr) * 144 + (ks * 16 + lc) * 2);
        ldsm_x4(qh[ks][0], qh[ks][1], qh[ks][2], qh[ks][3], sb + AT_KH + off);
        ldsm_x4(ql[ks][0], ql[ks][1], ql[ks][2], ql[ks][3], sb + AT_KL + off);
    }
    __syncthreads();

    // ---- prefetch KV tile 0 ----
    {
        #pragma unroll
        for (int i = 0; i < 4; ++i) {
            int idx = tid + i * 256;
            int row = idx >> 3, g = idx & 7;
            size_t go = (size_t)(kbase + row) * INNER + hcol + g * 8;
            uint32_t so = (uint32_t)(row * 144 + g * 16);
            cp16(sb + AT_KH + so, kh_ + go);
            cp16(sb + AT_KL + so, kl_ + go);
            cp16(sb + AT_VH + so, vh_ + go);
            cp16(sb + AT_VL + so, vl_ + go);
        }
        cp_commit();
    }

    float mrow[2] = {-CUDART_INF_F, -CUDART_INF_F};
    float lrow[2] = {0.f, 0.f};
    float oacc[8][4];
    #pragma unroll
    for (int ni = 0; ni < 8; ++ni)
        #pragma unroll
        for (int r = 0; r < 4; ++r) oacc[ni][r] = 0.f;

    for (int jt = 0; jt < NK / 128; ++jt) {
        const uint32_t bufo = (uint32_t)((jt & 1) * AT_BUF);
        const bool more = (jt + 1 < NK / 128);
        if (more) {
            const int krn = kbase + (jt + 1) * 128;
            const uint32_t nb = (uint32_t)(((jt + 1) & 1) * AT_BUF);
            #pragma unroll
            for (int i = 0; i < 4; ++i) {
                int idx = tid + i * 256;
                int row = idx >> 3, g = idx & 7;
                size_t go = (size_t)(krn + row) * INNER + hcol + g * 8;
                uint32_t so = (uint32_t)(row * 144 + g * 16);
                cp16(sb + nb + AT_KH + so, kh_ + go);
                cp16(sb + nb + AT_KL + so, kl_ + go);
                cp16(sb + nb + AT_VH + so, vh_ + go);
                cp16(sb + nb + AT_VL + so, vl_ + go);
            }
            cp_commit();
            cp_wait<1>();
        } else {
            cp_wait<0>();
        }
        __syncthreads();

        // ---- S = Q K^T (3-MMA split) ----
        float sacc[16][4];
        #pragma unroll
        for (int ni = 0; ni < 16; ++ni)
            #pragma unroll
            for (int r = 0; r < 4; ++r) sacc[ni][r] = 0.f;

        #pragma unroll
        for (int ks = 0; ks < 4; ++ks) {
            #pragma unroll
            for (int nt = 0; nt < 8; ++nt) {
                uint32_t off = (uint32_t)((nt * 16 + lr) * 144 + (ks * 16 + lc) * 2);
                uint32_t kh0, kh1, kh2, kh3, kl0, kl1, kl2, kl3;
                ldsm_x4(kh0, kh1, kh2, kh3, sb + bufo + AT_KH + off);
                ldsm_x4(kl0, kl1, kl2, kl3, sb + bufo + AT_KL + off);
                uint32_t khr[4] = {kh0, kh1, kh2, kh3};
                uint32_t klr[4] = {kl0, kl1, kl2, kl3};
                #pragma unroll
                for (int sel = 0; sel < 2; ++sel) {
                    int ni = nt * 2 + sel;
                    mma16816(sacc[ni], qh[ks], khr[sel], khr[sel + 2]);
                    mma16816(sacc[ni], qh[ks], klr[sel], klr[sel + 2]);
                    mma16816(sacc[ni], ql[ks], khr[sel], khr[sel + 2]);
                }
            }
        }

        // ---- online softmax (exp2 domain) ----
        #pragma unroll
        for (int half = 0; half < 2; ++half) {
            const int c0 = half * 2, c1 = half * 2 + 1;
            float rmax = -CUDART_INF_F;
            #pragma unroll
            for (int ni = 0; ni < 16; ++ni)
                rmax = fmaxf(rmax, fmaxf(sacc[ni][c0], sacc[ni][c1]));
            rmax = fmaxf(rmax, __shfl_xor_sync(0xffffffffu, rmax, 1));
            rmax = fmaxf(rmax, __shfl_xor_sync(0xffffffffu, rmax, 2));
            float nm    = fmaxf(mrow[half], rmax);
            float alpha = exp2f(mrow[half] - nm);
            mrow[half] = nm;

            float rsum = 0.f;
            #pragma unroll
            for (int ni = 0; ni < 16; ++ni) {
                sacc[ni][c0] = exp2f(sacc[ni][c0] - nm);
                sacc[ni][c1] = exp2f(sacc[ni][c1] - nm);
                rsum += sacc[ni][c0] + sacc[ni][c1];
            }
            rsum += __shfl_xor_sync(0xffffffffu, rsum, 1);
            rsum += __shfl_xor_sync(0xffffffffu, rsum, 2);

            lrow[half] = lrow[half] * alpha + rsum;
            #pragma unroll
            for (int ni = 0; ni < 8; ++ni) {
                oacc[ni][c0] *= alpha;
                oacc[ni][c1] *= alpha;
            }
        }

        // ---- O += P V (P split in regs; V via ldmatrix.trans) ----
        #pragma unroll
        for (int ks2 = 0; ks2 < 8; ++ks2) {
            const int e = ks2 * 2, od = ks2 * 2 + 1;
            float p00 = sacc[e][0],  p01 = sacc[e][1],  p10 = sacc[e][2],  p11 = sacc[e][3];
            float r00 = sacc[od][0], r01 = sacc[od][1], r10 = sacc[od][2], r11 = sacc[od][3];
            uint32_t ph[4] = {packbf2(p00, p01), packbf2(p10, p11),
                              packbf2(r00, r01), packbf2(r10, r11)};
            uint32_t pl[4] = {packbf2(p00 - bfhi(p00), p01 - bfhi(p01)),
                              packbf2(p10 - bfhi(p10), p11 - bfhi(p11)),
                              packbf2(r00 - bfhi(r00), r01 - bfhi(r01)),
                              packbf2(r10 - bfhi(r10), r11 - bfhi(r11))};
            #pragma unroll
            for (int vt = 0; vt < 4; ++vt) {
                uint32_t off = (uint32_t)((ks2 * 16 + lr) * 144 + (vt * 16 + lc) * 2);
                uint32_t vh0, vh1, vh2, vh3, vl0, vl1, vl2, vl3;
                ldsm_x4_t(vh0, vh1, vh2, vh3, sb + bufo + AT_VH + off);
                ldsm_x4_t(vl0, vl1, vl2, vl3, sb + bufo + AT_VL + off);
                mma16816(oacc[vt * 2 + 0], ph, vh0, vh1);
                mma16816(oacc[vt * 2 + 0], pl, vh0, vh1);
                mma16816(oacc[vt * 2 + 0], ph, vl0, vl1);
                mma16816(oacc[vt * 2 + 1], ph, vh2, vh3);
                mma16816(oacc[vt * 2 + 1], pl, vh2, vh3);
                mma16816(oacc[vt * 2 + 1], ph, vl2, vl3);
            }
        }
        __syncthreads();
    }

    // ---- normalize + write split bf16 (head-merged) ----
    const float inv0 = 1.0f / lrow[0];
    const float inv1 = 1.0f / lrow[1];
    const int row0 = qbase + wq + (lane >> 2);
    #pragma unroll
    for (int ni = 0; ni < 8; ++ni) {
        int col = hcol + ni * 8 + (lane & 3) * 2;
        float v0 = oacc[ni][0] * inv0, v1 = oacc[ni][1] * inv0;
        float v2 = oacc[ni][2] * inv1, v3 = oacc[ni][3] * inv1;
        *(uint32_t*)&aoh[(size_t)row0 * INNER + col] = packbf2(v0, v1);
        *(uint32_t*)&aol[(size_t)row0 * INNER + col] =
            packbf2(v0 - bfhi(v0), v1 - bfhi(v1));
        *(uint32_t*)&aoh[(size_t)(row0 + 8) * INNER + col] = packbf2(v2, v3);
        *(uint32_t*)&aol[(size_t)(row0 + 8) * INNER + col] =
            packbf2(v2 - bfhi(v2), v3 - bfhi(v3));
    }
}

// ---------------------------------------------------------------------------
// Launch
// ---------------------------------------------------------------------------
extern "C" void kernel_launch(void* const* d_in, const int* in_sizes, int n_in,
                              void* d_out, int out_size)
{
    (void)in_sizes; (void)n_in; (void)out_size;
    const float* x   = (const float*)d_in[0];
    const float* ctx = (const float*)d_in[1];
    const float* Wq  = (const float*)d_in[2];
    const float* Wk  = (const float*)d_in[3];
    const float* Wv  = (const float*)d_in[4];
    const float* Wo  = (const float*)d_in[5];
    const float* bo  = (const float*)d_in[6];
    float* out = (float*)d_out;

    __nv_bfloat16 *xh, *xl, *ch, *cl, *qh, *ql, *kh, *kl, *vh, *vl, *aoh, *aol;
    __nv_bfloat16 *wthi, *wtlo;
    (void)cudaGetSymbolAddress((void**)&xh,  g_xh);  (void)cudaGetSymbolAddress((void**)&xl,  g_xl);
    (void)cudaGetSymbolAddress((void**)&ch,  g_ch);  (void)cudaGetSymbolAddress((void**)&cl,  g_cl);
    (void)cudaGetSymbolAddress((void**)&qh,  g_qh);  (void)cudaGetSymbolAddress((void**)&ql,  g_ql);
    (void)cudaGetSymbolAddress((void**)&kh,  g_kh);  (void)cudaGetSymbolAddress((void**)&kl,  g_kl);
    (void)cudaGetSymbolAddress((void**)&vh,  g_vh);  (void)cudaGetSymbolAddress((void**)&vl,  g_vl);
    (void)cudaGetSymbolAddress((void**)&aoh, g_aoh); (void)cudaGetSymbolAddress((void**)&aol, g_aol);
    (void)cudaGetSymbolAddress((void**)&wthi, g_wthi);
    (void)cudaGetSymbolAddress((void**)&wtlo, g_wtlo);

    (void)cudaFuncSetAttribute(attn_mma,
                               cudaFuncAttributeMaxDynamicSharedMemorySize, ATTN_SMEM);
    (void)cudaFuncSetAttribute(proj_qkv,
                               cudaFuncAttributeMaxDynamicSharedMemorySize, GEMM_SMEM);
    (void)cudaFuncSetAttribute(proj_o,
                               cudaFuncAttributeMaxDynamicSharedMemorySize, GEMM_SMEM);

    // 1) weight transpose+split (one launch)
    wsplit_all<<<dim3(24, 16, 4), 256>>>(Wq, Wk, Wv, Wo, wthi, wtlo);

    // 2) activation split (one launch)
    asplit_all<<<(NX4 + NC4 + 255) / 256, 256>>>(x, ctx, xh, xl, ch, cl);

    // 3) Q/K/V projections (one launch, 512 CTAs)
    proj_qkv<<<dim3(4, 128), 256, GEMM_SMEM>>>(xh, xl, ch, cl, wthi, wtlo,
                                               qh, ql, kh, kl, vh, vl);

    // 4) attention
    attn_mma<<<dim3(NQ / 128, B_ * HEADS), 256, ATTN_SMEM>>>(qh, ql, kh, kl, vh, vl, aoh, aol);

    // 5) output projection + bias -> d_out
    proj_o<<<dim3(4, 64), 256, GEMM_SMEM>>>(aoh, aol, wthi, wtlo, bo, out);
}

// round 14
// speedup vs baseline: 1.4877x; 1.4877x over previous
#include <cuda_runtime.h>
#include <cuda_bf16.h>
#include <math_constants.h>
#include <cstdint>

// ---------------------------------------------------------------------------
// CrossAttention: out = softmax((xWq)(ctxWk)^T * scale) (ctxWv) Wo + bo
// Round 13: revert GEMM occupancy-2 (register spills caused the R12/13
// regression); attention restructured to 128-thread CTAs (64 q-rows),
// single KV buffer, 2 CTAs/SM for cross-CTA latency hiding.
// ---------------------------------------------------------------------------

#define B_     4
#define NQ     2048
#define NK     1024
#define DQ     512
#define DC     768
#define HEADS  8
#define DHEAD  64
#define INNER  512
#define MQ_ALL (B_*NQ)        // 8192
#define MK_ALL (B_*NK)        // 4096
#define QSCALE (0.125f * 1.44269504f)   // head scale * log2(e)

// pre-split activations / intermediates (bf16 hi/lo pairs)
__device__ __nv_bfloat16 g_xh [MQ_ALL * DQ],    g_xl [MQ_ALL * DQ];
__device__ __nv_bfloat16 g_ch [MK_ALL * DC],    g_cl [MK_ALL * DC];
__device__ __nv_bfloat16 g_qh [MQ_ALL * INNER], g_ql [MQ_ALL * INNER];
__device__ __nv_bfloat16 g_kh [MK_ALL * INNER], g_kl [MK_ALL * INNER];
__device__ __nv_bfloat16 g_vh [MK_ALL * INNER], g_vl [MK_ALL * INNER];
__device__ __nv_bfloat16 g_aoh[MQ_ALL * INNER], g_aol[MQ_ALL * INNER];

// transposed+split weights [N][K]
#define OFF_WQ 0
#define OFF_WK (512*512)
#define OFF_WV (OFF_WK + 512*768)
#define OFF_WO (OFF_WV + 512*768)
#define WT_TOTAL (OFF_WO + 512*512)
__device__ __nv_bfloat16 g_wthi[WT_TOTAL];
__device__ __nv_bfloat16 g_wtlo[WT_TOTAL];

// ---------------------------------------------------------------------------
// helpers
// ---------------------------------------------------------------------------
__device__ __forceinline__ uint32_t smem_u32(const void* p) {
    uint32_t a;
    asm("{ .reg .u64 t; cvta.to.shared.u64 t, %1; cvt.u32.u64 %0, t; }"
        : "=r"(a) : "l"(p));
    return a;
}
__device__ __forceinline__ void cp16(uint32_t saddr, const void* g) {
    asm volatile("cp.async.cg.shared.global [%0], [%1], 16;"
                 :: "r"(saddr), "l"(g));
}
__device__ __forceinline__ void cp_commit() {
    asm volatile("cp.async.commit_group;" ::: "memory");
}
template <int N> __device__ __forceinline__ void cp_wait() {
    asm volatile("cp.async.wait_group %0;" :: "n"(N) : "memory");
}
__device__ __forceinline__ void ldsm_x4(uint32_t& r0, uint32_t& r1,
                                        uint32_t& r2, uint32_t& r3, uint32_t addr) {
    asm volatile("ldmatrix.sync.aligned.m8n8.x4.shared.b16 {%0,%1,%2,%3}, [%4];"
                 : "=r"(r0), "=r"(r1), "=r"(r2), "=r"(r3) : "r"(addr));
}
__device__ __forceinline__ void ldsm_x4_t(uint32_t& r0, uint32_t& r1,
                                          uint32_t& r2, uint32_t& r3, uint32_t addr) {
    asm volatile("ldmatrix.sync.aligned.m8n8.x4.trans.shared.b16 {%0,%1,%2,%3}, [%4];"
                 : "=r"(r0), "=r"(r1), "=r"(r2), "=r"(r3) : "r"(addr));
}
__device__ __forceinline__ void mma16816(float* c, const uint32_t* a,
                                         uint32_t b0, uint32_t b1) {
    asm volatile(
        "mma.sync.aligned.m16n8k16.row.col.f32.bf16.bf16.f32 "
        "{%0,%1,%2,%3}, {%4,%5,%6,%7}, {%8,%9}, {%0,%1,%2,%3};"
        : "+f"(c[0]), "+f"(c[1]), "+f"(c[2]), "+f"(c[3])
        : "r"(a[0]), "r"(a[1]), "r"(a[2]), "r"(a[3]), "r"(b0), "r"(b1));
}
__device__ __forceinline__ uint32_t packbf2(float a, float b) {
    __nv_bfloat162 t = __floats2bfloat162_rn(a, b);
    return *reinterpret_cast<uint32_t*>(&t);
}
__device__ __forceinline__ float bfhi(float x) {
    return __bfloat162float(__float2bfloat16(x));
}

// ---------------------------------------------------------------------------
// Merged weight transpose+split: all 4 weights in one launch (z selects).
// ---------------------------------------------------------------------------
__global__ void __launch_bounds__(256)
wsplit_all(const float* __restrict__ Wq, const float* __restrict__ Wk,
           const float* __restrict__ Wv, const float* __restrict__ Wo,
           __nv_bfloat16* __restrict__ hi, __nv_bfloat16* __restrict__ lo)
{
    const float* W; __nv_bfloat16 *H, *L; int K, N;
    switch (blockIdx.z) {
        case 0: W = Wq; H = hi + OFF_WQ; L = lo + OFF_WQ; K = DQ;    N = INNER; break;
        case 1: W = Wk; H = hi + OFF_WK; L = lo + OFF_WK; K = DC;    N = INNER; break;
        case 2: W = Wv; H = hi + OFF_WV; L = lo + OFF_WV; K = DC;    N = INNER; break;
        default:W = Wo; H = hi + OFF_WO; L = lo + OFF_WO; K = INNER; N = DQ;    break;
    }
    const int k0 = blockIdx.x * 32, n0 = blockIdx.y * 32;
    if (k0 >= K) return;
    __shared__ float t[32][33];
    const int tx = threadIdx.x & 31, ty = threadIdx.x >> 5;
    #pragma unroll
    for (int i = 0; i < 32; i += 8)
        t[ty + i][tx] = W[(size_t)(k0 + ty + i) * N + n0 + tx];
    __syncthreads();
    #pragma unroll
    for (int i = 0; i < 32; i += 8) {
        float x = t[tx][ty + i];
        __nv_bfloat16 h = __float2bfloat16(x);
        __nv_bfloat16 l = __float2bfloat16(x - __bfloat162float(h));
        size_t o = (size_t)(n0 + ty + i) * K + k0 + tx;
        H[o] = h; L[o] = l;
    }
}

// ---------------------------------------------------------------------------
// Merged activation split: x then ctx in one grid.
// ---------------------------------------------------------------------------
#define NX4 (MQ_ALL * DQ / 4)      // 1048576
#define NC4 (MK_ALL * DC / 4)      // 786432

__global__ void __launch_bounds__(256)
asplit_all(const float* __restrict__ X, const float* __restrict__ CTX,
           __nv_bfloat16* __restrict__ xh, __nv_bfloat16* __restrict__ xl,
           __nv_bfloat16* __restrict__ chp, __nv_bfloat16* __restrict__ clp)
{
    int i = blockIdx.x * 256 + threadIdx.x;
    const float* A; __nv_bfloat16 *H, *L;
    if (i < NX4) { A = X; H = xh; L = xl; }
    else if (i < NX4 + NC4) { i -= NX4; A = CTX; H = chp; L = clp; }
    else return;
    float4 v = ((const float4*)A)[i];
    ((uint2*)H)[i] = make_uint2(packbf2(v.x, v.y), packbf2(v.z, v.w));
    ((uint2*)L)[i] = make_uint2(packbf2(v.x - bfhi(v.x), v.y - bfhi(v.y)),
                                packbf2(v.z - bfhi(v.z), v.w - bfhi(v.w)));
}

// ---------------------------------------------------------------------------
// GEMM core (all-bf16 operands, split 3-MMA). Occupancy 1 (NO reg cap —
// the occ-2 cap at 128 regs spilled and regressed R13).
// ---------------------------------------------------------------------------
#define GS_AH 0
#define GS_AL 10240
#define GS_BH 20480
#define GS_BL 30720
#define GS_BUF 40960
#define GEMM_SMEM (2 * GS_BUF)

__device__ __forceinline__ void
gemm_core(const __nv_bfloat16* __restrict__ Ahi, const __nv_bfloat16* __restrict__ Alo,
          const __nv_bfloat16* __restrict__ Bhi, const __nv_bfloat16* __restrict__ Blo,
          const float* __restrict__ bias, float* __restrict__ Cf,
          __nv_bfloat16* __restrict__ Chi, __nv_bfloat16* __restrict__ Clo,
          float scale, int K, int m0, int n0, char* smem)
{
    const uint32_t sb = smem_u32(smem);
    const int tid  = threadIdx.x;
    const int lane = tid & 31;
    const int wid  = tid >> 5;
    const int wm   = (wid & 1) * 64;
    const int wn   = (wid >> 1) * 32;

    float acc[4][4][4];
    #pragma unroll
    for (int mi = 0; mi < 4; ++mi)
        #pragma unroll
        for (int ni = 0; ni < 4; ++ni)
            #pragma unroll
            for (int r = 0; r < 4; ++r) acc[mi][ni][r] = 0.f;

    const int nch = K >> 5;
    const int lr = lane & 15;
    const int lc = (lane >> 4) << 3;

    #pragma unroll
    for (int i = 0; i < 2; ++i) {
        int idx = tid + i * 256;
        int row = idx >> 2, g = idx & 3;
        uint32_t so = (uint32_t)(row * 80 + g * 16);
        cp16(sb + GS_AH + so, Ahi + (size_t)(m0 + row) * K + g * 8);
        cp16(sb + GS_AL + so, Alo + (size_t)(m0 + row) * K + g * 8);
        cp16(sb + GS_BH + so, Bhi + (size_t)(n0 + row) * K + g * 8);
        cp16(sb + GS_BL + so, Blo + (size_t)(n0 + row) * K + g * 8);
    }
    cp_commit();

    for (int c = 0; c < nch; ++c) {
        const uint32_t bufo = (uint32_t)((c & 1) * GS_BUF);
        const bool more = (c + 1 < nch);
        if (more) {
            const int k0n = (c + 1) << 5;
            const uint32_t nb = (uint32_t)(((c + 1) & 1) * GS_BUF);
            #pragma unroll
            for (int i = 0; i < 2; ++i) {
                int idx = tid + i * 256;
                int row = idx >> 2, g = idx & 3;
                uint32_t so = (uint32_t)(row * 80 + g * 16);
                cp16(sb + nb + GS_AH + so, Ahi + (size_t)(m0 + row) * K + k0n + g * 8);
                cp16(sb + nb + GS_AL + so, Alo + (size_t)(m0 + row) * K + k0n + g * 8);
                cp16(sb + nb + GS_BH + so, Bhi + (size_t)(n0 + row) * K + k0n + g * 8);
                cp16(sb + nb + GS_BL + so, Blo + (size_t)(n0 + row) * K + k0n + g * 8);
            }
            cp_commit();
            cp_wait<1>();
        } else {
            cp_wait<0>();
        }
        __syncthreads();

        #pragma unroll
        for (int ks = 0; ks < 32; ks += 16) {
            uint32_t ah[4][4], al[4][4], bh[2][4], bl[2][4];
            #pragma unroll
            for (int mi = 0; mi < 4; ++mi) {
                uint32_t off = (uint32_t)((wm + mi * 16 + lr) * 80 + (ks + lc) * 2);
                ldsm_x4(ah[mi][0], ah[mi][1], ah[mi][2], ah[mi][3], sb + bufo + GS_AH + off);
                ldsm_x4(al[mi][0], al[mi][1], al[mi][2], al[mi][3], sb + bufo + GS_AL + off);
            }
            #pragma unroll
            for (int nt = 0; nt < 2; ++nt) {
                uint32_t off = (uint32_t)((wn + nt * 16 + lr) * 80 + (ks + lc) * 2);
                ldsm_x4(bh[nt][0], bh[nt][1], bh[nt][2], bh[nt][3], sb + bufo + GS_BH + off);
                ldsm_x4(bl[nt][0], bl[nt][1], bl[nt][2], bl[nt][3], sb + bufo + GS_BL + off);
            }
            #pragma unroll
            for (int mi = 0; mi < 4; ++mi)
                #pragma unroll
                for (int ni = 0; ni < 4; ++ni) {
                    int nt = ni >> 1, sel = ni & 1;
                    mma16816(acc[mi][ni], ah[mi], bh[nt][sel], bh[nt][sel + 2]);
                    mma16816(acc[mi][ni], ah[mi], bl[nt][sel], bl[nt][sel + 2]);
                    mma16816(acc[mi][ni], al[mi], bh[nt][sel], bh[nt][sel + 2]);
                }
        }
        __syncthreads();
    }

    const int qrow = lane >> 2;
    const int qcol = (lane & 3) * 2;
    #pragma unroll
    for (int mi = 0; mi < 4; ++mi) {
        #pragma unroll
        for (int ni = 0; ni < 4; ++ni) {
            int row0 = m0 + wm + mi * 16 + qrow;
            int col  = n0 + wn + ni * 8 + qcol;
            if (Cf) {
                float2 o0 = make_float2(acc[mi][ni][0], acc[mi][ni][1]);
                float2 o1 = make_float2(acc[mi][ni][2], acc[mi][ni][3]);
                float2 bb = *(const float2*)&bias[col];
                o0.x += bb.x; o0.y += bb.y;
                o1.x += bb.x; o1.y += bb.y;
                *(float2*)&Cf[(size_t)row0 * 512 + col]       = o0;
                *(float2*)&Cf[(size_t)(row0 + 8) * 512 + col] = o1;
            } else {
                float v0 = acc[mi][ni][0] * scale, v1 = acc[mi][ni][1] * scale;
                float v2 = acc[mi][ni][2] * scale, v3 = acc[mi][ni][3] * scale;
                *(uint32_t*)&Chi[(size_t)row0 * 512 + col] = packbf2(v0, v1);
                *(uint32_t*)&Clo[(size_t)row0 * 512 + col] =
                    packbf2(v0 - bfhi(v0), v1 - bfhi(v1));
                *(uint32_t*)&Chi[(size_t)(row0 + 8) * 512 + col] = packbf2(v2, v3);
                *(uint32_t*)&Clo[(size_t)(row0 + 8) * 512 + col] =
                    packbf2(v2 - bfhi(v2), v3 - bfhi(v3));
            }
        }
    }
}

// Merged Q/K/V projection: grid (4, 128). by<64: Q rows; by<96: K; else V.
__global__ void __launch_bounds__(256)
proj_qkv(const __nv_bfloat16* __restrict__ xh,  const __nv_bfloat16* __restrict__ xl,
         const __nv_bfloat16* __restrict__ ch,  const __nv_bfloat16* __restrict__ cl,
         const __nv_bfloat16* __restrict__ whi, const __nv_bfloat16* __restrict__ wlo,
         __nv_bfloat16* __restrict__ qh,  __nv_bfloat16* __restrict__ ql,
         __nv_bfloat16* __restrict__ kh,  __nv_bfloat16* __restrict__ kl,
         __nv_bfloat16* __restrict__ vh,  __nv_bfloat16* __restrict__ vl)
{
    extern __shared__ char smem[];
    const int by = blockIdx.y;
    const __nv_bfloat16 *Ah, *Al, *Bh, *Bl;
    __nv_bfloat16 *Oh, *Ol;
    float sc; int K, m0;
    if (by < 64) {
        Ah = xh; Al = xl; Bh = whi + OFF_WQ; Bl = wlo + OFF_WQ;
        Oh = qh; Ol = ql; sc = QSCALE; K = DQ; m0 = by * 128;
    } else if (by < 96) {
        Ah = ch; Al = cl; Bh = whi + OFF_WK; Bl = wlo + OFF_WK;
        Oh = kh; Ol = kl; sc = 1.0f; K = DC; m0 = (by - 64) * 128;
    } else {
        Ah = ch; Al = cl; Bh = whi + OFF_WV; Bl = wlo + OFF_WV;
        Oh = vh; Ol = vl; sc = 1.0f; K = DC; m0 = (by - 96) * 128;
    }
    gemm_core(Ah, Al, Bh, Bl, nullptr, nullptr, Oh, Ol, sc, K,
              m0, blockIdx.x * 128, smem);
}

// Output projection (fp32 + bias into d_out)
__global__ void __launch_bounds__(256)
proj_o(const __nv_bfloat16* __restrict__ aoh, const __nv_bfloat16* __restrict__ aol,
       const __nv_bfloat16* __restrict__ whi, const __nv_bfloat16* __restrict__ wlo,
       const float* __restrict__ bias, float* __restrict__ out)
{
    extern __shared__ char smem[];
    gemm_core(aoh, aol, whi + OFF_WO, wlo + OFF_WO, bias, out,
              nullptr, nullptr, 1.0f, INNER,
              blockIdx.y * 128, blockIdx.x * 128, smem);
}

// ---------------------------------------------------------------------------
// Flash attention: 128-thread CTA (4 warps x 16 q-rows = 64 q-rows),
// single KV buffer (73.7KB) -> 2 CTAs/SM. exp2 softmax. Grid (NQ/64, 32).
// smem: KH,KL,VH,VL each [128][72] bf16 (stride 144B).
// ---------------------------------------------------------------------------
#define AT_KH 0
#define AT_KL 18432
#define AT_VH 36864
#define AT_VL 55296
#define ATTN_SMEM 73728

__global__ void __launch_bounds__(128)
attn_mma(const __nv_bfloat16* __restrict__ qh_, const __nv_bfloat16* __restrict__ ql_,
         const __nv_bfloat16* __restrict__ kh_, const __nv_bfloat16* __restrict__ kl_,
         const __nv_bfloat16* __restrict__ vh_, const __nv_bfloat16* __restrict__ vl_,
         __nv_bfloat16* __restrict__ aoh, __nv_bfloat16* __restrict__ aol)
{
    extern __shared__ char smem[];
    const uint32_t sb = smem_u32(smem);
    const int tid  = threadIdx.x;
    const int lane = tid & 31;
    const int wid  = tid >> 5;          // 0..3
    const int wq   = wid * 16;          // q-row group within 64
    const int lr   = lane & 15;
    const int lc   = (lane >> 4) << 3;

    const int bh = blockIdx.y;
    const int b  = bh >> 3;
    const int h  = bh & 7;
    const int qbase = b * NQ + blockIdx.x * 64;
    const int kbase = b * NK;
    const int hcol  = h * DHEAD;

    // ---- stage Q tile (64 rows, pre-scaled, pre-split) through KH/KL ----
    #pragma unroll
    for (int i = 0; i < 4; ++i) {
        int idx = tid + i * 128;        // 0..511
        int row = idx >> 3, g = idx & 7;
        size_t go = (size_t)(qbase + row) * INNER + hcol + g * 8;
        uint32_t so = (uint32_t)(row * 144 + g * 16);
        *(uint4*)(smem + AT_KH + so) = *(const uint4*)&qh_[go];
        *(uint4*)(smem + AT_KL + so) = *(const uint4*)&ql_[go];
    }
    __syncthreads();

    uint32_t qh[4][4], ql[4][4];
    #pragma unroll
    for (int ks = 0; ks < 4; ++ks) {
        uint32_t off = (uint32_t)((wq + lr) * 144 + (ks * 16 + lc) * 2);
        ldsm_x4(qh[ks][0], qh[ks][1], qh[ks][2], qh[ks][3], sb + AT_KH + off);
        ldsm_x4(ql[ks][0], ql[ks][1], ql[ks][2], ql[ks][3], sb + AT_KL + off);
    }

    float mrow[2] = {-CUDART_INF_F, -CUDART_INF_F};
    float lrow[2] = {0.f, 0.f};
    float oacc[8][4];
    #pragma unroll
    for (int ni = 0; ni < 8; ++ni)
        #pragma unroll
        for (int r = 0; r < 4; ++r) oacc[ni][r] = 0.f;

    for (int jt = 0; jt < NK / 128; ++jt) {
        __syncthreads();   // previous tile reads (and Q staging) complete
        const int krow0 = kbase + jt * 128;
        #pragma unroll
        for (int i = 0; i < 8; ++i) {
            int idx = tid + i * 128;    // 0..1023
            int row = idx >> 3, g = idx & 7;
            size_t go = (size_t)(krow0 + row) * INNER + hcol + g * 8;
            uint32_t so = (uint32_t)(row * 144 + g * 16);
            cp16(sb + AT_KH + so, kh_ + go);
            cp16(sb + AT_KL + so, kl_ + go);
            cp16(sb + AT_VH + so, vh_ + go);
            cp16(sb + AT_VL + so, vl_ + go);
        }
        cp_commit();
        cp_wait<0>();
        __syncthreads();

        // ---- S = Q K^T (3-MMA split) ----
        float sacc[16][4];
        #pragma unroll
        for (int ni = 0; ni < 16; ++ni)
            #pragma unroll
            for (int r = 0; r < 4; ++r) sacc[ni][r] = 0.f;

        #pragma unroll
        for (int ks = 0; ks < 4; ++ks) {
            #pragma unroll
            for (int nt = 0; nt < 8; ++nt) {
                uint32_t off = (uint32_t)((nt * 16 + lr) * 144 + (ks * 16 + lc) * 2);
                uint32_t kh0, kh1, kh2, kh3, kl0, kl1, kl2, kl3;
                ldsm_x4(kh0, kh1, kh2, kh3, sb + AT_KH + off);
                ldsm_x4(kl0, kl1, kl2, kl3, sb + AT_KL + off);
                uint32_t khr[4] = {kh0, kh1, kh2, kh3};
                uint32_t klr[4] = {kl0, kl1, kl2, kl3};
                #pragma unroll
                for (int sel = 0; sel < 2; ++sel) {
                    int ni = nt * 2 + sel;
                    mma16816(sacc[ni], qh[ks], khr[sel], khr[sel + 2]);
                    mma16816(sacc[ni], qh[ks], klr[sel], klr[sel + 2]);
                    mma16816(sacc[ni], ql[ks], khr[sel], khr[sel + 2]);
                }
            }
        }

        // ---- online softmax (exp2 domain) ----
        #pragma unroll
        for (int half = 0; half < 2; ++half) {
            const int c0 = half * 2, c1 = half * 2 + 1;
            float rmax = -CUDART_INF_F;
            #pragma unroll
            for (int ni = 0; ni < 16; ++ni)
                rmax = fmaxf(rmax, fmaxf(sacc[ni][c0], sacc[ni][c1]));
            rmax = fmaxf(rmax, __shfl_xor_sync(0xffffffffu, rmax, 1));
            rmax = fmaxf(rmax, __shfl_xor_sync(0xffffffffu, rmax, 2));
            float nm    = fmaxf(mrow[half], rmax);
            float alpha = exp2f(mrow[half] - nm);
            mrow[half] = nm;

            float rsum = 0.f;
            #pragma unroll
            for (int ni = 0; ni < 16; ++ni) {
                sacc[ni][c0] = exp2f(sacc[ni][c0] - nm);
                sacc[ni][c1] = exp2f(sacc[ni][c1] - nm);
                rsum += sacc[ni][c0] + sacc[ni][c1];
            }
            rsum += __shfl_xor_sync(0xffffffffu, rsum, 1);
            rsum += __shfl_xor_sync(0xffffffffu, rsum, 2);

            lrow[half] = lrow[half] * alpha + rsum;
            #pragma unroll
            for (int ni = 0; ni < 8; ++ni) {
                oacc[ni][c0] *= alpha;
                oacc[ni][c1] *= alpha;
            }
        }

        // ---- O += P V (P split in regs; V via ldmatrix.trans) ----
        #pragma unroll
        for (int ks2 = 0; ks2 < 8; ++ks2) {
            const int e = ks2 * 2, od = ks2 * 2 + 1;
            float p00 = sacc[e][0],  p01 = sacc[e][1],  p10 = sacc[e][2],  p11 = sacc[e][3];
            float r00 = sacc[od][0], r01 = sacc[od][1], r10 = sacc[od][2], r11 = sacc[od][3];
            uint32_t ph[4] = {packbf2(p00, p01), packbf2(p10, p11),
                              packbf2(r00, r01), packbf2(r10, r11)};
            uint32_t pl[4] = {packbf2(p00 - bfhi(p00), p01 - bfhi(p01)),
                              packbf2(p10 - bfhi(p10), p11 - bfhi(p11)),
                              packbf2(r00 - bfhi(r00), r01 - bfhi(r01)),
                              packbf2(r10 - bfhi(r10), r11 - bfhi(r11))};
            #pragma unroll
            for (int vt = 0; vt < 4; ++vt) {
                uint32_t off = (uint32_t)((ks2 * 16 + lr) * 144 + (vt * 16 + lc) * 2);
                uint32_t vh0, vh1, vh2, vh3, vl0, vl1, vl2, vl3;
                ldsm_x4_t(vh0, vh1, vh2, vh3, sb + AT_VH + off);
                ldsm_x4_t(vl0, vl1, vl2, vl3, sb + AT_VL + off);
                mma16816(oacc[vt * 2 + 0], ph, vh0, vh1);
                mma16816(oacc[vt * 2 + 0], pl, vh0, vh1);
                mma16816(oacc[vt * 2 + 0], ph, vl0, vl1);
                mma16816(oacc[vt * 2 + 1], ph, vh2, vh3);
                mma16816(oacc[vt * 2 + 1], pl, vh2, vh3);
                mma16816(oacc[vt * 2 + 1], ph, vl2, vl3);
            }
        }
    }

    // ---- normalize + write split bf16 (head-merged) ----
    const float inv0 = 1.0f / lrow[0];
    const float inv1 = 1.0f / lrow[1];
    const int row0 = qbase + wq + (lane >> 2);
    #pragma unroll
    for (int ni = 0; ni < 8; ++ni) {
        int col = hcol + ni * 8 + (lane & 3) * 2;
        float v0 = oacc[ni][0] * inv0, v1 = oacc[ni][1] * inv0;
        float v2 = oacc[ni][2] * inv1, v3 = oacc[ni][3] * inv1;
        *(uint32_t*)&aoh[(size_t)row0 * INNER + col] = packbf2(v0, v1);
        *(uint32_t*)&aol[(size_t)row0 * INNER + col] =
            packbf2(v0 - bfhi(v0), v1 - bfhi(v1));
        *(uint32_t*)&aoh[(size_t)(row0 + 8) * INNER + col] = packbf2(v2, v3);
        *(uint32_t*)&aol[(size_t)(row0 + 8) * INNER + col] =
            packbf2(v2 - bfhi(v2), v3 - bfhi(v3));
    }
}

// ---------------------------------------------------------------------------
// Launch
// ---------------------------------------------------------------------------
extern "C" void kernel_launch(void* const* d_in, const int* in_sizes, int n_in,
                              void* d_out, int out_size)
{
    (void)in_sizes; (void)n_in; (void)out_size;
    const float* x   = (const float*)d_in[0];
    const float* ctx = (const float*)d_in[1];
    const float* Wq  = (const float*)d_in[2];
    const float* Wk  = (const float*)d_in[3];
    const float* Wv  = (const float*)d_in[4];
    const float* Wo  = (const float*)d_in[5];
    const float* bo  = (const float*)d_in[6];
    float* out = (float*)d_out;

    __nv_bfloat16 *xh, *xl, *ch, *cl, *qh, *ql, *kh, *kl, *vh, *vl, *aoh, *aol;
    __nv_bfloat16 *wthi, *wtlo;
    (void)cudaGetSymbolAddress((void**)&xh,  g_xh);  (void)cudaGetSymbolAddress((void**)&xl,  g_xl);
    (void)cudaGetSymbolAddress((void**)&ch,  g_ch);  (void)cudaGetSymbolAddress((void**)&cl,  g_cl);
    (void)cudaGetSymbolAddress((void**)&qh,  g_qh);  (void)cudaGetSymbolAddress((void**)&ql,  g_ql);
    (void)cudaGetSymbolAddress((void**)&kh,  g_kh);  (void)cudaGetSymbolAddress((void**)&kl,  g_kl);
    (void)cudaGetSymbolAddress((void**)&vh,  g_vh);  (void)cudaGetSymbolAddress((void**)&vl,  g_vl);
    (void)cudaGetSymbolAddress((void**)&aoh, g_aoh); (void)cudaGetSymbolAddress((void**)&aol, g_aol);
    (void)cudaGetSymbolAddress((void**)&wthi, g_wthi);
    (void)cudaGetSymbolAddress((void**)&wtlo, g_wtlo);

    (void)cudaFuncSetAttribute(attn_mma,
                               cudaFuncAttributeMaxDynamicSharedMemorySize, ATTN_SMEM);
    (void)cudaFuncSetAttribute(proj_qkv,
                               cudaFuncAttributeMaxDynamicSharedMemorySize, GEMM_SMEM);
    (void)cudaFuncSetAttribute(proj_o,
                               cudaFuncAttributeMaxDynamicSharedMemorySize, GEMM_SMEM);

    // 1) weight transpose+split (one launch)
    wsplit_all<<<dim3(24, 16, 4), 256>>>(Wq, Wk, Wv, Wo, wthi, wtlo);

    // 2) activation split (one launch)
    asplit_all<<<(NX4 + NC4 + 255) / 256, 256>>>(x, ctx, xh, xl, ch, cl);

    // 3) Q/K/V projections (one launch, 512 CTAs, occ 1 — no reg cap)
    proj_qkv<<<dim3(4, 128), 256, GEMM_SMEM>>>(xh, xl, ch, cl, wthi, wtlo,
                                               qh, ql, kh, kl, vh, vl);

    // 4) attention (1024 CTAs of 128 threads, 2 CTAs/SM)
    attn_mma<<<dim3(NQ / 64, B_ * HEADS), 128, ATTN_SMEM>>>(qh, ql, kh, kl, vh, vl, aoh, aol);

    // 5) output projection + bias -> d_out
    proj_o<<<dim3(4, 64), 256, GEMM_SMEM>>>(aoh, aol, wthi, wtlo, bo, out);
}

// round 17
// speedup vs baseline: 1.5697x; 1.0551x over previous
#include <cuda_runtime.h>
#include <cuda_bf16.h>
#include <math_constants.h>
#include <cstdint>

// ---------------------------------------------------------------------------
// CrossAttention: out = softmax((xWq)(ctxWk)^T * scale) (ctxWv) Wo + bo
// Round 16: R15 pipelined attention with the KV cp.async coverage bug fixed
// (K/V load loops were i<4 = 64 rows; must be i<8 = 128 rows at 128 thr).
// K double-buffered + V single-buffered, 110.6 KB/CTA, 2 CTAs/SM.
// ---------------------------------------------------------------------------

#define B_     4
#define NQ     2048
#define NK     1024
#define DQ     512
#define DC     768
#define HEADS  8
#define DHEAD  64
#define INNER  512
#define MQ_ALL (B_*NQ)        // 8192
#define MK_ALL (B_*NK)        // 4096
#define QSCALE (0.125f * 1.44269504f)   // head scale * log2(e)

// pre-split activations / intermediates (bf16 hi/lo pairs)
__device__ __nv_bfloat16 g_xh [MQ_ALL * DQ],    g_xl [MQ_ALL * DQ];
__device__ __nv_bfloat16 g_ch [MK_ALL * DC],    g_cl [MK_ALL * DC];
__device__ __nv_bfloat16 g_qh [MQ_ALL * INNER], g_ql [MQ_ALL * INNER];
__device__ __nv_bfloat16 g_kh [MK_ALL * INNER], g_kl [MK_ALL * INNER];
__device__ __nv_bfloat16 g_vh [MK_ALL * INNER], g_vl [MK_ALL * INNER];
__device__ __nv_bfloat16 g_aoh[MQ_ALL * INNER], g_aol[MQ_ALL * INNER];

// transposed+split weights [N][K]
#define OFF_WQ 0
#define OFF_WK (512*512)
#define OFF_WV (OFF_WK + 512*768)
#define OFF_WO (OFF_WV + 512*768)
#define WT_TOTAL (OFF_WO + 512*512)
__device__ __nv_bfloat16 g_wthi[WT_TOTAL];
__device__ __nv_bfloat16 g_wtlo[WT_TOTAL];

// ---------------------------------------------------------------------------
// helpers
// ---------------------------------------------------------------------------
__device__ __forceinline__ uint32_t smem_u32(const void* p) {
    uint32_t a;
    asm("{ .reg .u64 t; cvta.to.shared.u64 t, %1; cvt.u32.u64 %0, t; }"
        : "=r"(a) : "l"(p));
    return a;
}
__device__ __forceinline__ void cp16(uint32_t saddr, const void* g) {
    asm volatile("cp.async.cg.shared.global [%0], [%1], 16;"
                 :: "r"(saddr), "l"(g));
}
__device__ __forceinline__ void cp_commit() {
    asm volatile("cp.async.commit_group;" ::: "memory");
}
template <int N> __device__ __forceinline__ void cp_wait() {
    asm volatile("cp.async.wait_group %0;" :: "n"(N) : "memory");
}
__device__ __forceinline__ void ldsm_x4(uint32_t& r0, uint32_t& r1,
                                        uint32_t& r2, uint32_t& r3, uint32_t addr) {
    asm volatile("ldmatrix.sync.aligned.m8n8.x4.shared.b16 {%0,%1,%2,%3}, [%4];"
                 : "=r"(r0), "=r"(r1), "=r"(r2), "=r"(r3) : "r"(addr));
}
__device__ __forceinline__ void ldsm_x4_t(uint32_t& r0, uint32_t& r1,
                                          uint32_t& r2, uint32_t& r3, uint32_t addr) {
    asm volatile("ldmatrix.sync.aligned.m8n8.x4.trans.shared.b16 {%0,%1,%2,%3}, [%4];"
                 : "=r"(r0), "=r"(r1), "=r"(r2), "=r"(r3) : "r"(addr));
}
__device__ __forceinline__ void mma16816(float* c, const uint32_t* a,
                                         uint32_t b0, uint32_t b1) {
    asm volatile(
        "mma.sync.aligned.m16n8k16.row.col.f32.bf16.bf16.f32 "
        "{%0,%1,%2,%3}, {%4,%5,%6,%7}, {%8,%9}, {%0,%1,%2,%3};"
        : "+f"(c[0]), "+f"(c[1]), "+f"(c[2]), "+f"(c[3])
        : "r"(a[0]), "r"(a[1]), "r"(a[2]), "r"(a[3]), "r"(b0), "r"(b1));
}
__device__ __forceinline__ uint32_t packbf2(float a, float b) {
    __nv_bfloat162 t = __floats2bfloat162_rn(a, b);
    return *reinterpret_cast<uint32_t*>(&t);
}
__device__ __forceinline__ float bfhi(float x) {
    return __bfloat162float(__float2bfloat16(x));
}

// ---------------------------------------------------------------------------
// Merged weight transpose+split: all 4 weights in one launch (z selects).
// ---------------------------------------------------------------------------
__global__ void __launch_bounds__(256)
wsplit_all(const float* __restrict__ Wq, const float* __restrict__ Wk,
           const float* __restrict__ Wv, const float* __restrict__ Wo,
           __nv_bfloat16* __restrict__ hi, __nv_bfloat16* __restrict__ lo)
{
    const float* W; __nv_bfloat16 *H, *L; int K, N;
    switch (blockIdx.z) {
        case 0: W = Wq; H = hi + OFF_WQ; L = lo + OFF_WQ; K = DQ;    N = INNER; break;
        case 1: W = Wk; H = hi + OFF_WK; L = lo + OFF_WK; K = DC;    N = INNER; break;
        case 2: W = Wv; H = hi + OFF_WV; L = lo + OFF_WV; K = DC;    N = INNER; break;
        default:W = Wo; H = hi + OFF_WO; L = lo + OFF_WO; K = INNER; N = DQ;    break;
    }
    const int k0 = blockIdx.x * 32, n0 = blockIdx.y * 32;
    if (k0 >= K) return;
    __shared__ float t[32][33];
    const int tx = threadIdx.x & 31, ty = threadIdx.x >> 5;
    #pragma unroll
    for (int i = 0; i < 32; i += 8)
        t[ty + i][tx] = W[(size_t)(k0 + ty + i) * N + n0 + tx];
    __syncthreads();
    #pragma unroll
    for (int i = 0; i < 32; i += 8) {
        float x = t[tx][ty + i];
        __nv_bfloat16 h = __float2bfloat16(x);
        __nv_bfloat16 l = __float2bfloat16(x - __bfloat162float(h));
        size_t o = (size_t)(n0 + ty + i) * K + k0 + tx;
        H[o] = h; L[o] = l;
    }
}

// ---------------------------------------------------------------------------
// Merged activation split: x then ctx in one grid.
// ---------------------------------------------------------------------------
#define NX4 (MQ_ALL * DQ / 4)      // 1048576
#define NC4 (MK_ALL * DC / 4)      // 786432

__global__ void __launch_bounds__(256)
asplit_all(const float* __restrict__ X, const float* __restrict__ CTX,
           __nv_bfloat16* __restrict__ xh, __nv_bfloat16* __restrict__ xl,
           __nv_bfloat16* __restrict__ chp, __nv_bfloat16* __restrict__ clp)
{
    int i = blockIdx.x * 256 + threadIdx.x;
    const float* A; __nv_bfloat16 *H, *L;
    if (i < NX4) { A = X; H = xh; L = xl; }
    else if (i < NX4 + NC4) { i -= NX4; A = CTX; H = chp; L = clp; }
    else return;
    float4 v = ((const float4*)A)[i];
    ((uint2*)H)[i] = make_uint2(packbf2(v.x, v.y), packbf2(v.z, v.w));
    ((uint2*)L)[i] = make_uint2(packbf2(v.x - bfhi(v.x), v.y - bfhi(v.y)),
                                packbf2(v.z - bfhi(v.z), v.w - bfhi(v.w)));
}

// ---------------------------------------------------------------------------
// GEMM core (all-bf16 operands, split 3-MMA). Occupancy 1 (no reg cap).
// ---------------------------------------------------------------------------
#define GS_AH 0
#define GS_AL 10240
#define GS_BH 20480
#define GS_BL 30720
#define GS_BUF 40960
#define GEMM_SMEM (2 * GS_BUF)

__device__ __forceinline__ void
gemm_core(const __nv_bfloat16* __restrict__ Ahi, const __nv_bfloat16* __restrict__ Alo,
          const __nv_bfloat16* __restrict__ Bhi, const __nv_bfloat16* __restrict__ Blo,
          const float* __restrict__ bias, float* __restrict__ Cf,
          __nv_bfloat16* __restrict__ Chi, __nv_bfloat16* __restrict__ Clo,
          float scale, int K, int m0, int n0, char* smem)
{
    const uint32_t sb = smem_u32(smem);
    const int tid  = threadIdx.x;
    const int lane = tid & 31;
    const int wid  = tid >> 5;
    const int wm   = (wid & 1) * 64;
    const int wn   = (wid >> 1) * 32;

    float acc[4][4][4];
    #pragma unroll
    for (int mi = 0; mi < 4; ++mi)
        #pragma unroll
        for (int ni = 0; ni < 4; ++ni)
            #pragma unroll
            for (int r = 0; r < 4; ++r) acc[mi][ni][r] = 0.f;

    const int nch = K >> 5;
    const int lr = lane & 15;
    const int lc = (lane >> 4) << 3;

    #pragma unroll
    for (int i = 0; i < 2; ++i) {
        int idx = tid + i * 256;
        int row = idx >> 2, g = idx & 3;
        uint32_t so = (uint32_t)(row * 80 + g * 16);
        cp16(sb + GS_AH + so, Ahi + (size_t)(m0 + row) * K + g * 8);
        cp16(sb + GS_AL + so, Alo + (size_t)(m0 + row) * K + g * 8);
        cp16(sb + GS_BH + so, Bhi + (size_t)(n0 + row) * K + g * 8);
        cp16(sb + GS_BL + so, Blo + (size_t)(n0 + row) * K + g * 8);
    }
    cp_commit();

    for (int c = 0; c < nch; ++c) {
        const uint32_t bufo = (uint32_t)((c & 1) * GS_BUF);
        const bool more = (c + 1 < nch);
        if (more) {
            const int k0n = (c + 1) << 5;
            const uint32_t nb = (uint32_t)(((c + 1) & 1) * GS_BUF);
            #pragma unroll
            for (int i = 0; i < 2; ++i) {
                int idx = tid + i * 256;
                int row = idx >> 2, g = idx & 3;
                uint32_t so = (uint32_t)(row * 80 + g * 16);
                cp16(sb + nb + GS_AH + so, Ahi + (size_t)(m0 + row) * K + k0n + g * 8);
                cp16(sb + nb + GS_AL + so, Alo + (size_t)(m0 + row) * K + k0n + g * 8);
                cp16(sb + nb + GS_BH + so, Bhi + (size_t)(n0 + row) * K + k0n + g * 8);
                cp16(sb + nb + GS_BL + so, Blo + (size_t)(n0 + row) * K + k0n + g * 8);
            }
            cp_commit();
            cp_wait<1>();
        } else {
            cp_wait<0>();
        }
        __syncthreads();

        #pragma unroll
        for (int ks = 0; ks < 32; ks += 16) {
            uint32_t ah[4][4], al[4][4], bh[2][4], bl[2][4];
            #pragma unroll
            for (int mi = 0; mi < 4; ++mi) {
                uint32_t off = (uint32_t)((wm + mi * 16 + lr) * 80 + (ks + lc) * 2);
                ldsm_x4(ah[mi][0], ah[mi][1], ah[mi][2], ah[mi][3], sb + bufo + GS_AH + off);
                ldsm_x4(al[mi][0], al[mi][1], al[mi][2], al[mi][3], sb + bufo + GS_AL + off);
            }
            #pragma unroll
            for (int nt = 0; nt < 2; ++nt) {
                uint32_t off = (uint32_t)((wn + nt * 16 + lr) * 80 + (ks + lc) * 2);
                ldsm_x4(bh[nt][0], bh[nt][1], bh[nt][2], bh[nt][3], sb + bufo + GS_BH + off);
                ldsm_x4(bl[nt][0], bl[nt][1], bl[nt][2], bl[nt][3], sb + bufo + GS_BL + off);
            }
            #pragma unroll
            for (int mi = 0; mi < 4; ++mi)
                #pragma unroll
                for (int ni = 0; ni < 4; ++ni) {
                    int nt = ni >> 1, sel = ni & 1;
                    mma16816(acc[mi][ni], ah[mi], bh[nt][sel], bh[nt][sel + 2]);
                    mma16816(acc[mi][ni], ah[mi], bl[nt][sel], bl[nt][sel + 2]);
                    mma16816(acc[mi][ni], al[mi], bh[nt][sel], bh[nt][sel + 2]);
                }
        }
        __syncthreads();
    }

    const int qrow = lane >> 2;
    const int qcol = (lane & 3) * 2;
    #pragma unroll
    for (int mi = 0; mi < 4; ++mi) {
        #pragma unroll
        for (int ni = 0; ni < 4; ++ni) {
            int row0 = m0 + wm + mi * 16 + qrow;
            int col  = n0 + wn + ni * 8 + qcol;
            if (Cf) {
                float2 o0 = make_float2(acc[mi][ni][0], acc[mi][ni][1]);
                float2 o1 = make_float2(acc[mi][ni][2], acc[mi][ni][3]);
                float2 bb = *(const float2*)&bias[col];
                o0.x += bb.x; o0.y += bb.y;
                o1.x += bb.x; o1.y += bb.y;
                *(float2*)&Cf[(size_t)row0 * 512 + col]       = o0;
                *(float2*)&Cf[(size_t)(row0 + 8) * 512 + col] = o1;
            } else {
                float v0 = acc[mi][ni][0] * scale, v1 = acc[mi][ni][1] * scale;
                float v2 = acc[mi][ni][2] * scale, v3 = acc[mi][ni][3] * scale;
                *(uint32_t*)&Chi[(size_t)row0 * 512 + col] = packbf2(v0, v1);
                *(uint32_t*)&Clo[(size_t)row0 * 512 + col] =
                    packbf2(v0 - bfhi(v0), v1 - bfhi(v1));
                *(uint32_t*)&Chi[(size_t)(row0 + 8) * 512 + col] = packbf2(v2, v3);
                *(uint32_t*)&Clo[(size_t)(row0 + 8) * 512 + col] =
                    packbf2(v2 - bfhi(v2), v3 - bfhi(v3));
            }
        }
    }
}

// Merged Q/K/V projection: grid (4, 128). by<64: Q rows; by<96: K; else V.
__global__ void __launch_bounds__(256)
proj_qkv(const __nv_bfloat16* __restrict__ xh,  const __nv_bfloat16* __restrict__ xl,
         const __nv_bfloat16* __restrict__ ch,  const __nv_bfloat16* __restrict__ cl,
         const __nv_bfloat16* __restrict__ whi, const __nv_bfloat16* __restrict__ wlo,
         __nv_bfloat16* __restrict__ qh,  __nv_bfloat16* __restrict__ ql,
         __nv_bfloat16* __restrict__ kh,  __nv_bfloat16* __restrict__ kl,
         __nv_bfloat16* __restrict__ vh,  __nv_bfloat16* __restrict__ vl)
{
    extern __shared__ char smem[];
    const int by = blockIdx.y;
    const __nv_bfloat16 *Ah, *Al, *Bh, *Bl;
    __nv_bfloat16 *Oh, *Ol;
    float sc; int K, m0;
    if (by < 64) {
        Ah = xh; Al = xl; Bh = whi + OFF_WQ; Bl = wlo + OFF_WQ;
        Oh = qh; Ol = ql; sc = QSCALE; K = DQ; m0 = by * 128;
    } else if (by < 96) {
        Ah = ch; Al = cl; Bh = whi + OFF_WK; Bl = wlo + OFF_WK;
        Oh = kh; Ol = kl; sc = 1.0f; K = DC; m0 = (by - 64) * 128;
    } else {
        Ah = ch; Al = cl; Bh = whi + OFF_WV; Bl = wlo + OFF_WV;
        Oh = vh; Ol = vl; sc = 1.0f; K = DC; m0 = (by - 96) * 128;
    }
    gemm_core(Ah, Al, Bh, Bl, nullptr, nullptr, Oh, Ol, sc, K,
              m0, blockIdx.x * 128, smem);
}

// Output projection (fp32 + bias into d_out)
__global__ void __launch_bounds__(256)
proj_o(const __nv_bfloat16* __restrict__ aoh, const __nv_bfloat16* __restrict__ aol,
       const __nv_bfloat16* __restrict__ whi, const __nv_bfloat16* __restrict__ wlo,
       const float* __restrict__ bias, float* __restrict__ out)
{
    extern __shared__ char smem[];
    gemm_core(aoh, aol, whi + OFF_WO, wlo + OFF_WO, bias, out,
              nullptr, nullptr, 1.0f, INNER,
              blockIdx.y * 128, blockIdx.x * 128, smem);
}

// ---------------------------------------------------------------------------
// Flash attention: 128-thread CTA, 64 q-rows, 2 CTAs/SM.
// K double-buffered + V single-buffered, pipelined cp.async:
//   V(t) load hides behind S=QK(t); K(t+1) load hides behind softmax+PV(t).
// smem: Kbuf0 [KH|KL] 36864, Kbuf1 36864, V [VH|VL] 36864 = 110592 B.
// Each K/V part load = 128 rows x 8 groups = 1024 cp16 slots = i<8 @128thr.
// ---------------------------------------------------------------------------
#define AT_KHO 0
#define AT_KLO 18432
#define AT_KBUF 36864
#define AT_VH 73728
#define AT_VL 92160
#define ATTN_SMEM 110592

__global__ void __launch_bounds__(128)
attn_mma(const __nv_bfloat16* __restrict__ qh_, const __nv_bfloat16* __restrict__ ql_,
         const __nv_bfloat16* __restrict__ kh_, const __nv_bfloat16* __restrict__ kl_,
         const __nv_bfloat16* __restrict__ vh_, const __nv_bfloat16* __restrict__ vl_,
         __nv_bfloat16* __restrict__ aoh, __nv_bfloat16* __restrict__ aol)
{
    extern __shared__ char smem[];
    const uint32_t sb = smem_u32(smem);
    const int tid  = threadIdx.x;
    const int lane = tid & 31;
    const int wid  = tid >> 5;          // 0..3
    const int wq   = wid * 16;
    const int lr   = lane & 15;
    const int lc   = (lane >> 4) << 3;

    const int bh = blockIdx.y;
    const int b  = bh >> 3;
    const int h  = bh & 7;
    const int qbase = b * NQ + blockIdx.x * 64;
    const int kbase = b * NK;
    const int hcol  = h * DHEAD;

    // ---- stage Q tile (64 rows -> i<4 is correct here) through K buffer 0 ----
    #pragma unroll
    for (int i = 0; i < 4; ++i) {
        int idx = tid + i * 128;        // 0..511: 64 rows x 8 groups
        int row = idx >> 3, g = idx & 7;
        size_t go = (size_t)(qbase + row) * INNER + hcol + g * 8;
        uint32_t so = (uint32_t)(row * 144 + g * 16);
        *(uint4*)(smem + AT_KHO + so) = *(const uint4*)&qh_[go];
        *(uint4*)(smem + AT_KLO + so) = *(const uint4*)&ql_[go];
    }
    __syncthreads();

    uint32_t qh[4][4], ql[4][4];
    #pragma unroll
    for (int ks = 0; ks < 4; ++ks) {
        uint32_t off = (uint32_t)((wq + lr) * 144 + (ks * 16 + lc) * 2);
        ldsm_x4(qh[ks][0], qh[ks][1], qh[ks][2], qh[ks][3], sb + AT_KHO + off);
        ldsm_x4(ql[ks][0], ql[ks][1], ql[ks][2], ql[ks][3], sb + AT_KLO + off);
    }
    __syncthreads();   // Q frags consumed before K(0) cp.async overwrites buf0

    // ---- issue K(0) into buffer 0 (128 rows: i<8) ----
    #pragma unroll
    for (int i = 0; i < 8; ++i) {
        int idx = tid + i * 128;        // 0..1023: 128 rows x 8 groups
        int row = idx >> 3, g = idx & 7;
        size_t go = (size_t)(kbase + row) * INNER + hcol + g * 8;
        uint32_t so = (uint32_t)(row * 144 + g * 16);
        cp16(sb + AT_KHO + so, kh_ + go);
        cp16(sb + AT_KLO + so, kl_ + go);
    }
    cp_commit();

    float mrow[2] = {-CUDART_INF_F, -CUDART_INF_F};
    float lrow[2] = {0.f, 0.f};
    float oacc[8][4];
    #pragma unroll
    for (int ni = 0; ni < 8; ++ni)
        #pragma unroll
        for (int r = 0; r < 4; ++r) oacc[ni][r] = 0.f;

    for (int jt = 0; jt < NK / 128; ++jt) {
        const uint32_t kb = sb + (uint32_t)((jt & 1) * AT_KBUF);
        const bool more = (jt + 1 < NK / 128);
        const int krow0 = kbase + jt * 128;

        __syncthreads();   // all warps done with V(jt-1) and K(jt-1) reads

        // issue V(jt) (128 rows: i<8); buffer free since PV(jt-1) completed
        #pragma unroll
        for (int i = 0; i < 8; ++i) {
            int idx = tid + i * 128;
            int row = idx >> 3, g = idx & 7;
            size_t go = (size_t)(krow0 + row) * INNER + hcol + g * 8;
            uint32_t so = (uint32_t)(row * 144 + g * 16);
            cp16(sb + AT_VH + so, vh_ + go);
            cp16(sb + AT_VL + so, vl_ + go);
        }
        cp_commit();

        cp_wait<1>();      // K(jt) complete (V(jt) still in flight)
        __syncthreads();

        // ---- S = Q K^T (3-MMA split), overlapping the V(jt) load ----
        float sacc[16][4];
        #pragma unroll
        for (int ni = 0; ni < 16; ++ni)
            #pragma unroll
            for (int r = 0; r < 4; ++r) sacc[ni][r] = 0.f;

        #pragma unroll
        for (int ks = 0; ks < 4; ++ks) {
            #pragma unroll
            for (int nt = 0; nt < 8; ++nt) {
                uint32_t off = (uint32_t)((nt * 16 + lr) * 144 + (ks * 16 + lc) * 2);
                uint32_t kh0, kh1, kh2, kh3, kl0, kl1, kl2, kl3;
                ldsm_x4(kh0, kh1, kh2, kh3, kb + AT_KHO + off);
                ldsm_x4(kl0, kl1, kl2, kl3, kb + AT_KLO + off);
                uint32_t khr[4] = {kh0, kh1, kh2, kh3};
                uint32_t klr[4] = {kl0, kl1, kl2, kl3};
                #pragma unroll
                for (int sel = 0; sel < 2; ++sel) {
                    int ni = nt * 2 + sel;
                    mma16816(sacc[ni], qh[ks], khr[sel], khr[sel + 2]);
                    mma16816(sacc[ni], qh[ks], klr[sel], klr[sel + 2]);
                    mma16816(sacc[ni], ql[ks], khr[sel], khr[sel + 2]);
                }
            }
        }

        // issue K(jt+1) (128 rows: i<8) into the alternate buffer
        if (more) {
            const uint32_t nkb = sb + (uint32_t)(((jt + 1) & 1) * AT_KBUF);
            const int krn = kbase + (jt + 1) * 128;
            #pragma unroll
            for (int i = 0; i < 8; ++i) {
                int idx = tid + i * 128;
                int row = idx >> 3, g = idx & 7;
                size_t go = (size_t)(krn + row) * INNER + hcol + g * 8;
                uint32_t so = (uint32_t)(row * 144 + g * 16);
                cp16(nkb + AT_KHO + so, kh_ + go);
                cp16(nkb + AT_KLO + so, kl_ + go);
            }
            cp_commit();
        }

        // ---- online softmax (exp2 domain), overlapping the K(jt+1) load ----
        #pragma unroll
        for (int half = 0; half < 2; ++half) {
            const int c0 = half * 2, c1 = half * 2 + 1;
            float rmax = -CUDART_INF_F;
            #pragma unroll
            for (int ni = 0; ni < 16; ++ni)
                rmax = fmaxf(rmax, fmaxf(sacc[ni][c0], sacc[ni][c1]));
            rmax = fmaxf(rmax, __shfl_xor_sync(0xffffffffu, rmax, 1));
            rmax = fmaxf(rmax, __shfl_xor_sync(0xffffffffu, rmax, 2));
            float nm    = fmaxf(mrow[half], rmax);
            float alpha = exp2f(mrow[half] - nm);
            mrow[half] = nm;

            float rsum = 0.f;
            #pragma unroll
            for (int ni = 0; ni < 16; ++ni) {
                sacc[ni][c0] = exp2f(sacc[ni][c0] - nm);
                sacc[ni][c1] = exp2f(sacc[ni][c1] - nm);
                rsum += sacc[ni][c0] + sacc[ni][c1];
            }
            rsum += __shfl_xor_sync(0xffffffffu, rsum, 1);
            rsum += __shfl_xor_sync(0xffffffffu, rsum, 2);

            lrow[half] = lrow[half] * alpha + rsum;
            #pragma unroll
            for (int ni = 0; ni < 8; ++ni) {
                oacc[ni][c0] *= alpha;
                oacc[ni][c1] *= alpha;
            }
        }

        if (more) cp_wait<1>();   // V(jt) complete (K(jt+1) still in flight)
        else      cp_wait<0>();   // last tile: drain everything
        __syncthreads();

        // ---- O += P V (P split in regs; V via ldmatrix.trans) ----
        #pragma unroll
        for (int ks2 = 0; ks2 < 8; ++ks2) {
            const int e = ks2 * 2, od = ks2 * 2 + 1;
            float p00 = sacc[e][0],  p01 = sacc[e][1],  p10 = sacc[e][2],  p11 = sacc[e][3];
            float r00 = sacc[od][0], r01 = sacc[od][1], r10 = sacc[od][2], r11 = sacc[od][3];
            uint32_t ph[4] = {packbf2(p00, p01), packbf2(p10, p11),
                              packbf2(r00, r01), packbf2(r10, r11)};
            uint32_t pl[4] = {packbf2(p00 - bfhi(p00), p01 - bfhi(p01)),
                              packbf2(p10 - bfhi(p10), p11 - bfhi(p11)),
                              packbf2(r00 - bfhi(r00), r01 - bfhi(r01)),
                              packbf2(r10 - bfhi(r10), r11 - bfhi(r11))};
            #pragma unroll
            for (int vt = 0; vt < 4; ++vt) {
                uint32_t off = (uint32_t)((ks2 * 16 + lr) * 144 + (vt * 16 + lc) * 2);
                uint32_t vh0, vh1, vh2, vh3, vl0, vl1, vl2, vl3;
                ldsm_x4_t(vh0, vh1, vh2, vh3, sb + AT_VH + off);
                ldsm_x4_t(vl0, vl1, vl2, vl3, sb + AT_VL + off);
                mma16816(oacc[vt * 2 + 0], ph, vh0, vh1);
                mma16816(oacc[vt * 2 + 0], pl, vh0, vh1);
                mma16816(oacc[vt * 2 + 0], ph, vl0, vl1);
                mma16816(oacc[vt * 2 + 1], ph, vh2, vh3);
                mma16816(oacc[vt * 2 + 1], pl, vh2, vh3);
                mma16816(oacc[vt * 2 + 1], ph, vl2, vl3);
            }
        }
    }

    // ---- normalize + write split bf16 (head-merged) ----
    const float inv0 = 1.0f / lrow[0];
    const float inv1 = 1.0f / lrow[1];
    const int row0 = qbase + wq + (lane >> 2);
    #pragma unroll
    for (int ni = 0; ni < 8; ++ni) {
        int col = hcol + ni * 8 + (lane & 3) * 2;
        float v0 = oacc[ni][0] * inv0, v1 = oacc[ni][1] * inv0;
        float v2 = oacc[ni][2] * inv1, v3 = oacc[ni][3] * inv1;
        *(uint32_t*)&aoh[(size_t)row0 * INNER + col] = packbf2(v0, v1);
        *(uint32_t*)&aol[(size_t)row0 * INNER + col] =
            packbf2(v0 - bfhi(v0), v1 - bfhi(v1));
        *(uint32_t*)&aoh[(size_t)(row0 + 8) * INNER + col] = packbf2(v2, v3);
        *(uint32_t*)&aol[(size_t)(row0 + 8) * INNER + col] =
            packbf2(v2 - bfhi(v2), v3 - bfhi(v3));
    }
}

// ---------------------------------------------------------------------------
// Launch
// ---------------------------------------------------------------------------
extern "C" void kernel_launch(void* const* d_in, const int* in_sizes, int n_in,
                              void* d_out, int out_size)
{
    (void)in_sizes; (void)n_in; (void)out_size;
    const float* x   = (const float*)d_in[0];
    const float* ctx = (const float*)d_in[1];
    const float* Wq  = (const float*)d_in[2];
    const float* Wk  = (const float*)d_in[3];
    const float* Wv  = (const float*)d_in[4];
    const float* Wo  = (const float*)d_in[5];
    const float* bo  = (const float*)d_in[6];
    float* out = (float*)d_out;

    __nv_bfloat16 *xh, *xl, *ch, *cl, *qh, *ql, *kh, *kl, *vh, *vl, *aoh, *aol;
    __nv_bfloat16 *wthi, *wtlo;
    (void)cudaGetSymbolAddress((void**)&xh,  g_xh);  (void)cudaGetSymbolAddress((void**)&xl,  g_xl);
    (void)cudaGetSymbolAddress((void**)&ch,  g_ch);  (void)cudaGetSymbolAddress((void**)&cl,  g_cl);
    (void)cudaGetSymbolAddress((void**)&qh,  g_qh);  (void)cudaGetSymbolAddress((void**)&ql,  g_ql);
    (void)cudaGetSymbolAddress((void**)&kh,  g_kh);  (void)cudaGetSymbolAddress((void**)&kl,  g_kl);
    (void)cudaGetSymbolAddress((void**)&vh,  g_vh);  (void)cudaGetSymbolAddress((void**)&vl,  g_vl);
    (void)cudaGetSymbolAddress((void**)&aoh, g_aoh); (void)cudaGetSymbolAddress((void**)&aol, g_aol);
    (void)cudaGetSymbolAddress((void**)&wthi, g_wthi);
    (void)cudaGetSymbolAddress((void**)&wtlo, g_wtlo);

    (void)cudaFuncSetAttribute(attn_mma,
                               cudaFuncAttributeMaxDynamicSharedMemorySize, ATTN_SMEM);
    (void)cudaFuncSetAttribute(proj_qkv,
                               cudaFuncAttributeMaxDynamicSharedMemorySize, GEMM_SMEM);
    (void)cudaFuncSetAttribute(proj_o,
                               cudaFuncAttributeMaxDynamicSharedMemorySize, GEMM_SMEM);

    // 1) weight transpose+split (one launch)
    wsplit_all<<<dim3(24, 16, 4), 256>>>(Wq, Wk, Wv, Wo, wthi, wtlo);

    // 2) activation split (one launch)
    asplit_all<<<(NX4 + NC4 + 255) / 256, 256>>>(x, ctx, xh, xl, ch, cl);

    // 3) Q/K/V projections (one launch, 512 CTAs)
    proj_qkv<<<dim3(4, 128), 256, GEMM_SMEM>>>(xh, xl, ch, cl, wthi, wtlo,
                                               qh, ql, kh, kl, vh, vl);

    // 4) attention (1024 CTAs of 128 threads, 2 CTAs/SM, pipelined KV)
    attn_mma<<<dim3(NQ / 64, B_ * HEADS), 128, ATTN_SMEM>>>(qh, ql, kh, kl, vh, vl, aoh, aol);

    // 5) output projection + bias -> d_out
    proj_o<<<dim3(4, 64), 256, GEMM_SMEM>>>(aoh, aol, wthi, wtlo, bo, out);
}